// round 13
// baseline (speedup 1.0000x reference)
#include <cuda_runtime.h>
#include <cuda_bf16.h>
#include <cstdint>

// BinaryConv2d via warp-level HMMA implicit GEMM (mma.sync m16n8k16 bf16).
// R13 = R12 with 16B-aligned layout (ldmatrix requirement): ODD_OFS = 5200.
//   (a) 4 independent mma accumulator chains (split x nc), depth 9 each
//   (b) B fragments via one ldmatrix.x4 per (tap,nc)
//   (c) staging keeps R11's 2-way STS conflict (alignment > bank tweak)
//
// smem row layout: even input col c at (c/2)*80; odd col at ODD_OFS+(c/2)*80.
// Column slot: split0 = k0..15 bf16 (32B), split1 at +32B. 16B chunks
// {k0-7 s0, k8-15 s0, k0-7 s1, k8-15 s1} = ldmatrix.x4 matrices 0..3.

#define OUT_HW   512
#define ODD_OFS  5200            // 65*80, 16B-aligned
#define ROWBYTES 10320           // 5200 even + 5120 odd region, 16B multiple

__global__ void __launch_bounds__(128)
binconv_mma(const float* __restrict__ x,
            const float* __restrict__ w,
            float* __restrict__ out) {
    __shared__ __align__(16) unsigned char s_x[3 * ROWBYTES];   // 30960 B

    const int tid  = threadIdx.x;
    const int wrp  = tid >> 5;
    const int lane = tid & 31;
    const int g    = lane >> 2;       // fragment group (oc row / px col)
    const int i4   = lane & 3;        // fragment sub-index

    const int n   = blockIdx.z;
    const int x0  = blockIdx.x * 64;  // output px base
    const int oy0 = blockIdx.y * 8;
    const int gx0 = 2 * x0 - 1;       // input col of tile col 0

    const float* xn = x + ((size_t)n << 24);

    // ---- A fragments: signs as bf16 +/-1, register-resident all kernel ----
    uint32_t sA[9][4];
    #pragma unroll
    for (int tap = 0; tap < 9; ++tap) {
        #pragma unroll
        for (int q = 0; q < 4; ++q) {
            int oc = g + (q & 1) * 8;
            int c  = 2 * i4 + (q >> 1) * 8;
            uint32_t lo = (w[oc * 144 + c * 9 + tap]       == 1.f) ? 0x3F80u : 0xBF80u;
            uint32_t hi = (w[oc * 144 + (c + 1) * 9 + tap] == 1.f) ? 0x3F80u : 0xBF80u;
            sA[tap][q] = lo | (hi << 16);
        }
    }

    // ---- stage one input row (16 channels, both bf16 splits) ----
    auto stage = [&](int ia) {
        unsigned char* rb = s_x + ((ia + 3) % 3) * ROWBYTES;
        const int cp = tid >> 4;
        const float* p0 = xn + ((size_t)(2 * cp) << 20) + ((size_t)(ia < 0 ? 0 : ia) << 10);
        const float* p1 = p0 + (1 << 20);
        const bool rv = (ia >= 0);
        #pragma unroll
        for (int v = 0; v < 9; ++v) {
            int col = (tid & 15) + 16 * v;
            if (col < 129) {
                int gx = gx0 + col;
                bool ok = rv && ((unsigned)gx < 1024u);
                float a = 0.f, b = 0.f;
                if (ok) { a = p0[gx]; b = p1[gx]; }
                __nv_bfloat16 ah = __float2bfloat16(a);
                __nv_bfloat16 bh = __float2bfloat16(b);
                __nv_bfloat16 al = __float2bfloat16(a - __bfloat162float(ah));
                __nv_bfloat16 bl = __float2bfloat16(b - __bfloat162float(bh));
                unsigned char* d = rb + (col >> 1) * 80
                                      + ((col & 1) ? ODD_OFS : 0) + cp * 4;
                *(__nv_bfloat162*)(d)      = __halves2bfloat162(ah, bh);  // split 0
                *(__nv_bfloat162*)(d + 32) = __halves2bfloat162(al, bl);  // split 1
            }
        }
    };

    // lane-constant ldmatrix pointer part:
    // px-col slot (wrp*16 + lane&7) + 16B chunk select (lane>>3)
    uint32_t sbase;
    asm("{ .reg .u64 t; cvta.to.shared.u64 t, %1; cvt.u32.u64 %0, t; }"
        : "=r"(sbase) : "l"((const void*)s_x));
    const uint32_t lane_off =
        (uint32_t)(wrp * 16 + (lane & 7)) * 80u + (uint32_t)(lane >> 3) * 16u;
    // tap j -> byte offset of input col (2p+j) relative to even slot p
    const uint32_t offj[3] = { 0u, (uint32_t)ODD_OFS, 80u };

    #pragma unroll 1
    for (int it = 0; it < 8; ++it) {
        const int oy  = oy0 + it;
        const int iy0 = 2 * oy - 1;

        if (it == 0) { stage(iy0); stage(iy0 + 1); stage(iy0 + 2); }
        else         { stage(iy0 + 1); stage(iy0 + 2); }
        __syncthreads();

        uint32_t rb3[3];
        #pragma unroll
        for (int r = 0; r < 3; ++r)
            rb3[r] = sbase + (uint32_t)(((iy0 + r + 3) % 3) * ROWBYTES) + lane_off;

        // 4 independent accumulator chains: [split][nc]
        float acc[2][2][4];
        #pragma unroll
        for (int s = 0; s < 2; ++s)
            #pragma unroll
            for (int nc = 0; nc < 2; ++nc)
                acc[s][nc][0] = acc[s][nc][1] = acc[s][nc][2] = acc[s][nc][3] = 0.f;

        #pragma unroll
        for (int tap = 0; tap < 9; ++tap) {
            const int r = tap / 3;
            const int j = tap % 3;
            uint32_t bb[2][4];
            #pragma unroll
            for (int nc = 0; nc < 2; ++nc) {
                uint32_t addr = rb3[r] + offj[j] + (uint32_t)nc * 640u;
                asm volatile(
                    "ldmatrix.sync.aligned.m8n8.x4.shared.b16 {%0,%1,%2,%3}, [%4];"
                    : "=r"(bb[nc][0]), "=r"(bb[nc][1]),
                      "=r"(bb[nc][2]), "=r"(bb[nc][3])
                    : "r"(addr));
            }
            #pragma unroll
            for (int nc = 0; nc < 2; ++nc) {
                asm("mma.sync.aligned.m16n8k16.row.col.f32.bf16.bf16.f32 "
                    "{%0,%1,%2,%3}, {%4,%5,%6,%7}, {%8,%9}, {%0,%1,%2,%3};"
                    : "+f"(acc[0][nc][0]), "+f"(acc[0][nc][1]),
                      "+f"(acc[0][nc][2]), "+f"(acc[0][nc][3])
                    : "r"(sA[tap][0]), "r"(sA[tap][1]),
                      "r"(sA[tap][2]), "r"(sA[tap][3]),
                      "r"(bb[nc][0]), "r"(bb[nc][1]));
                asm("mma.sync.aligned.m16n8k16.row.col.f32.bf16.bf16.f32 "
                    "{%0,%1,%2,%3}, {%4,%5,%6,%7}, {%8,%9}, {%0,%1,%2,%3};"
                    : "+f"(acc[1][nc][0]), "+f"(acc[1][nc][1]),
                      "+f"(acc[1][nc][2]), "+f"(acc[1][nc][3])
                    : "r"(sA[tap][0]), "r"(sA[tap][1]),
                      "r"(sA[tap][2]), "r"(sA[tap][3]),
                      "r"(bb[nc][2]), "r"(bb[nc][3]));
            }
        }

        // ---- merge splits + store: regs 0,1 -> oc=g ; 2,3 -> oc=g+8 ----
        #pragma unroll
        for (int nc = 0; nc < 2; ++nc) {
            float f0 = acc[0][nc][0] + acc[1][nc][0];
            float f1 = acc[0][nc][1] + acc[1][nc][1];
            float f2 = acc[0][nc][2] + acc[1][nc][2];
            float f3 = acc[0][nc][3] + acc[1][nc][3];
            int px = x0 + wrp * 16 + nc * 8 + 2 * i4;
            float* o0 = out + (((size_t)(n * 16 + g) * OUT_HW) + oy) * OUT_HW + px;
            float* o1 = o0 + (size_t)8 * OUT_HW * OUT_HW;
            *(float2*)o0 = make_float2(f0, f1);
            *(float2*)o1 = make_float2(f2, f3);
        }
        __syncthreads();   // ring slots reused by next iteration's staging
    }
}

extern "C" void kernel_launch(void* const* d_in, const int* in_sizes, int n_in,
                              void* d_out, int out_size) {
    const float* x = (const float*)d_in[0];
    const float* w = (const float*)d_in[1];
    float* out = (float*)d_out;

    dim3 grid(8, 64, 8);    // 64-px x-tiles, 8-row y-groups, batch
    dim3 block(128);
    binconv_mma<<<grid, block>>>(x, w, out);
}

// round 14
// speedup vs baseline: 1.2967x; 1.2967x over previous
#include <cuda_runtime.h>
#include <cuda_bf16.h>
#include <cstdint>

// BinaryConv2d via warp-level HMMA implicit GEMM (mma.sync m16n8k16 bf16).
// R14 = R13 (aligned ldmatrix layout, 4 acc chains) with the scheduling fix:
//   - ldmatrix NOT volatile (compiler/ptxas may hoist; syncthreads orders smem)
//   - explicit tap double-buffer: load tap t+1 fragments during tap t mmas
//
// smem row layout: even input col c at (c/2)*80; odd col at ODD_OFS+(c/2)*80.
// Column slot: split0 = k0..15 bf16 (32B), split1 at +32B. 16B chunks
// {k0-7 s0, k8-15 s0, k0-7 s1, k8-15 s1} = ldmatrix.x4 matrices 0..3.

#define OUT_HW   512
#define ODD_OFS  5200            // 65*80, 16B-aligned
#define ROWBYTES 10320

__device__ __forceinline__ void ldmx4(uint32_t* r, uint32_t addr) {
    asm("ldmatrix.sync.aligned.m8n8.x4.shared.b16 {%0,%1,%2,%3}, [%4];"
        : "=r"(r[0]), "=r"(r[1]), "=r"(r[2]), "=r"(r[3])
        : "r"(addr));
}

__global__ void __launch_bounds__(128)
binconv_mma(const float* __restrict__ x,
            const float* __restrict__ w,
            float* __restrict__ out) {
    __shared__ __align__(16) unsigned char s_x[3 * ROWBYTES];   // 30960 B

    const int tid  = threadIdx.x;
    const int wrp  = tid >> 5;
    const int lane = tid & 31;
    const int g    = lane >> 2;
    const int i4   = lane & 3;

    const int n   = blockIdx.z;
    const int x0  = blockIdx.x * 64;
    const int oy0 = blockIdx.y * 8;
    const int gx0 = 2 * x0 - 1;

    const float* xn = x + ((size_t)n << 24);

    // ---- A fragments: signs as bf16 +/-1, register-resident ----
    uint32_t sA[9][4];
    #pragma unroll
    for (int tap = 0; tap < 9; ++tap) {
        #pragma unroll
        for (int q = 0; q < 4; ++q) {
            int oc = g + (q & 1) * 8;
            int c  = 2 * i4 + (q >> 1) * 8;
            uint32_t lo = (w[oc * 144 + c * 9 + tap]       == 1.f) ? 0x3F80u : 0xBF80u;
            uint32_t hi = (w[oc * 144 + (c + 1) * 9 + tap] == 1.f) ? 0x3F80u : 0xBF80u;
            sA[tap][q] = lo | (hi << 16);
        }
    }

    // ---- stage one input row (16 channels, both bf16 splits) ----
    auto stage = [&](int ia) {
        unsigned char* rb = s_x + ((ia + 3) % 3) * ROWBYTES;
        const int cp = tid >> 4;
        const float* p0 = xn + ((size_t)(2 * cp) << 20) + ((size_t)(ia < 0 ? 0 : ia) << 10);
        const float* p1 = p0 + (1 << 20);
        const bool rv = (ia >= 0);
        #pragma unroll
        for (int v = 0; v < 9; ++v) {
            int col = (tid & 15) + 16 * v;
            if (col < 129) {
                int gx = gx0 + col;
                bool ok = rv && ((unsigned)gx < 1024u);
                float a = 0.f, b = 0.f;
                if (ok) { a = p0[gx]; b = p1[gx]; }
                __nv_bfloat16 ah = __float2bfloat16(a);
                __nv_bfloat16 bh = __float2bfloat16(b);
                __nv_bfloat16 al = __float2bfloat16(a - __bfloat162float(ah));
                __nv_bfloat16 bl = __float2bfloat16(b - __bfloat162float(bh));
                unsigned char* d = rb + (col >> 1) * 80
                                      + ((col & 1) ? ODD_OFS : 0) + cp * 4;
                *(__nv_bfloat162*)(d)      = __halves2bfloat162(ah, bh);
                *(__nv_bfloat162*)(d + 32) = __halves2bfloat162(al, bl);
            }
        }
    };

    uint32_t sbase;
    asm("{ .reg .u64 t; cvta.to.shared.u64 t, %1; cvt.u32.u64 %0, t; }"
        : "=r"(sbase) : "l"((const void*)s_x));
    const uint32_t lane_off =
        (uint32_t)(wrp * 16 + (lane & 7)) * 80u + (uint32_t)(lane >> 3) * 16u;
    const uint32_t offj[3] = { 0u, (uint32_t)ODD_OFS, 80u };

    #pragma unroll 1
    for (int it = 0; it < 8; ++it) {
        const int oy  = oy0 + it;
        const int iy0 = 2 * oy - 1;

        if (it == 0) { stage(iy0); stage(iy0 + 1); stage(iy0 + 2); }
        else         { stage(iy0 + 1); stage(iy0 + 2); }
        __syncthreads();

        uint32_t rb3[3];
        #pragma unroll
        for (int r = 0; r < 3; ++r)
            rb3[r] = sbase + (uint32_t)(((iy0 + r + 3) % 3) * ROWBYTES) + lane_off;

        // B address for tap t, nc
        auto baddr = [&](int tap, int nc) -> uint32_t {
            return rb3[tap / 3] + offj[tap % 3] + (uint32_t)nc * 640u;
        };

        float acc[2][2][4];
        #pragma unroll
        for (int s = 0; s < 2; ++s)
            #pragma unroll
            for (int nc = 0; nc < 2; ++nc)
                acc[s][nc][0] = acc[s][nc][1] = acc[s][nc][2] = acc[s][nc][3] = 0.f;

        // ---- tap double-buffered pipeline ----
        uint32_t bb[2][2][4];     // [buf][nc][frag]
        ldmx4(bb[0][0], baddr(0, 0));
        ldmx4(bb[0][1], baddr(0, 1));

        #pragma unroll
        for (int tap = 0; tap < 9; ++tap) {
            const int cur = tap & 1;
            if (tap < 8) {
                ldmx4(bb[cur ^ 1][0], baddr(tap + 1, 0));
                ldmx4(bb[cur ^ 1][1], baddr(tap + 1, 1));
            }
            #pragma unroll
            for (int nc = 0; nc < 2; ++nc) {
                asm("mma.sync.aligned.m16n8k16.row.col.f32.bf16.bf16.f32 "
                    "{%0,%1,%2,%3}, {%4,%5,%6,%7}, {%8,%9}, {%0,%1,%2,%3};"
                    : "+f"(acc[0][nc][0]), "+f"(acc[0][nc][1]),
                      "+f"(acc[0][nc][2]), "+f"(acc[0][nc][3])
                    : "r"(sA[tap][0]), "r"(sA[tap][1]),
                      "r"(sA[tap][2]), "r"(sA[tap][3]),
                      "r"(bb[cur][nc][0]), "r"(bb[cur][nc][1]));
                asm("mma.sync.aligned.m16n8k16.row.col.f32.bf16.bf16.f32 "
                    "{%0,%1,%2,%3}, {%4,%5,%6,%7}, {%8,%9}, {%0,%1,%2,%3};"
                    : "+f"(acc[1][nc][0]), "+f"(acc[1][nc][1]),
                      "+f"(acc[1][nc][2]), "+f"(acc[1][nc][3])
                    : "r"(sA[tap][0]), "r"(sA[tap][1]),
                      "r"(sA[tap][2]), "r"(sA[tap][3]),
                      "r"(bb[cur][nc][2]), "r"(bb[cur][nc][3]));
            }
        }

        // ---- merge splits + store ----
        #pragma unroll
        for (int nc = 0; nc < 2; ++nc) {
            float f0 = acc[0][nc][0] + acc[1][nc][0];
            float f1 = acc[0][nc][1] + acc[1][nc][1];
            float f2 = acc[0][nc][2] + acc[1][nc][2];
            float f3 = acc[0][nc][3] + acc[1][nc][3];
            int px = x0 + wrp * 16 + nc * 8 + 2 * i4;
            float* o0 = out + (((size_t)(n * 16 + g) * OUT_HW) + oy) * OUT_HW + px;
            float* o1 = o0 + (size_t)8 * OUT_HW * OUT_HW;
            *(float2*)o0 = make_float2(f0, f1);
            *(float2*)o1 = make_float2(f2, f3);
        }
        __syncthreads();
    }
}

extern "C" void kernel_launch(void* const* d_in, const int* in_sizes, int n_in,
                              void* d_out, int out_size) {
    const float* x = (const float*)d_in[0];
    const float* w = (const float*)d_in[1];
    float* out = (float*)d_out;

    dim3 grid(8, 64, 8);
    dim3 block(128);
    binconv_mma<<<grid, block>>>(x, w, out);
}

// round 15
// speedup vs baseline: 1.4558x; 1.1227x over previous
#include <cuda_runtime.h>
#include <cuda_fp16.h>
#include <cstdint>

// BinaryConv2d via warp-level HMMA implicit GEMM (mma.sync m16n8k16 f16).
// R15: SINGLE fp16 conversion of x (per-term rel err ~2^-12; +/-1 products
// exact; fp32 accumulate -> global rel err ~1e-4, tolerance 1e-3).
//   - mma count 18/iter (halved), one ldmatrix.x4 per tap serves both nc
//   - staging: float2 LDG pairs + one cvt.rn.f16x2 + one STS per column
//   - col slot = 16 ch x 2B = 32B at 48B stride (ldmatrix conflict-free),
//     even cols at q*48, odd cols at ODD_OFS + q*48

#define OUT_HW   512
#define CSTRIDE  48
#define ODD_OFS  3120            // 65 * 48, 16B-aligned
#define ROWBYTES 6192            // 3120 + 64*48

__device__ __forceinline__ void ldmx4(uint32_t* r, uint32_t addr) {
    asm("ldmatrix.sync.aligned.m8n8.x4.shared.b16 {%0,%1,%2,%3}, [%4];"
        : "=r"(r[0]), "=r"(r[1]), "=r"(r[2]), "=r"(r[3])
        : "r"(addr));
}

__global__ void __launch_bounds__(128)
binconv_mma(const float* __restrict__ x,
            const float* __restrict__ w,
            float* __restrict__ out) {
    __shared__ __align__(16) unsigned char s_x[3 * ROWBYTES];   // 18576 B

    const int tid  = threadIdx.x;
    const int wrp  = tid >> 5;
    const int lane = tid & 31;
    const int g    = lane >> 2;
    const int i4   = lane & 3;

    const int n   = blockIdx.z;
    const int x0  = blockIdx.x * 64;
    const int oy0 = blockIdx.y * 8;
    const int gx0 = 2 * x0 - 1;       // global input col of tile col 0

    const float* xn = x + ((size_t)n << 24);

    // ---- A fragments: signs as fp16 +/-1, register-resident ----
    uint32_t sA[9][4];
    #pragma unroll
    for (int tap = 0; tap < 9; ++tap) {
        #pragma unroll
        for (int q = 0; q < 4; ++q) {
            int oc = g + (q & 1) * 8;
            int c  = 2 * i4 + (q >> 1) * 8;
            uint32_t lo = (w[oc * 144 + c * 9 + tap]       == 1.f) ? 0x3C00u : 0xBC00u;
            uint32_t hi = (w[oc * 144 + (c + 1) * 9 + tap] == 1.f) ? 0x3C00u : 0xBC00u;
            sA[tap][q] = lo | (hi << 16);
        }
    }

    // ---- stage one input row: 16 channels, single fp16 ----
    // thread: channel pair cp = tid>>4; columns via (tid&15)
    auto stage = [&](int ia) {
        unsigned char* rb = s_x + ((ia + 3) % 3) * ROWBYTES;
        const int cp = tid >> 4;
        const float* p0 = xn + ((size_t)(2 * cp) << 20)
                             + ((size_t)(ia < 0 ? 0 : ia) << 10);
        const float* p1 = p0 + (1 << 20);
        const bool rv = (ia >= 0);

        // tile col 0 (odd global col gx0; zero when x0==0)
        if ((tid & 15) == 0) {
            bool ok = rv && (gx0 >= 0);
            float a = 0.f, b = 0.f;
            if (ok) { a = p0[gx0]; b = p1[gx0]; }
            *(__half2*)(rb + cp * 4) = __floats2half2_rn(a, b);
        }
        // col pairs (1+2m, 2+2m), m = 0..63; float2 loads are 8B-aligned
        #pragma unroll
        for (int v = 0; v < 4; ++v) {
            int m  = (tid & 15) + 16 * v;
            int gx = 2 * x0 + 2 * m;              // global col of tile col 1+2m
            float2 a2 = make_float2(0.f, 0.f);
            float2 b2 = make_float2(0.f, 0.f);
            if (rv) {
                a2 = *(const float2*)(p0 + gx);
                b2 = *(const float2*)(p1 + gx);
            }
            __half2 h1 = __floats2half2_rn(a2.x, b2.x);   // tile col 1+2m (odd, q=m)
            __half2 h2 = __floats2half2_rn(a2.y, b2.y);   // tile col 2+2m (even, q=m+1)
            *(__half2*)(rb + ODD_OFS + m * CSTRIDE + cp * 4) = h1;
            *(__half2*)(rb + (m + 1) * CSTRIDE + cp * 4)     = h2;
        }
    };

    uint32_t sbase;
    asm("{ .reg .u64 t; cvta.to.shared.u64 t, %1; cvt.u32.u64 %0, t; }"
        : "=r"(sbase) : "l"((const void*)s_x));
    // ldmatrix.x4 lane addressing: m0/m1 = nc0 chunk0/1, m2/m3 = nc1 chunk0/1
    const uint32_t pslot =
        (uint32_t)(wrp * 16 + (lane & 7) + ((lane >> 4) << 3));
    const uint32_t lane_off = pslot * CSTRIDE + (uint32_t)((lane >> 3) & 1) * 16u;
    const uint32_t offj[3] = { 0u, (uint32_t)ODD_OFS, (uint32_t)CSTRIDE };

    #pragma unroll 1
    for (int it = 0; it < 8; ++it) {
        const int oy  = oy0 + it;
        const int iy0 = 2 * oy - 1;

        if (it == 0) { stage(iy0); stage(iy0 + 1); stage(iy0 + 2); }
        else         { stage(iy0 + 1); stage(iy0 + 2); }
        __syncthreads();

        uint32_t rb3[3];
        #pragma unroll
        for (int r = 0; r < 3; ++r)
            rb3[r] = sbase + (uint32_t)(((iy0 + r + 3) % 3) * ROWBYTES) + lane_off;

        float acc[2][4];
        #pragma unroll
        for (int nc = 0; nc < 2; ++nc)
            acc[nc][0] = acc[nc][1] = acc[nc][2] = acc[nc][3] = 0.f;

        #pragma unroll
        for (int tap = 0; tap < 9; ++tap) {
            uint32_t bb[4];
            ldmx4(bb, rb3[tap / 3] + offj[tap % 3]);
            asm("mma.sync.aligned.m16n8k16.row.col.f32.f16.f16.f32 "
                "{%0,%1,%2,%3}, {%4,%5,%6,%7}, {%8,%9}, {%0,%1,%2,%3};"
                : "+f"(acc[0][0]), "+f"(acc[0][1]), "+f"(acc[0][2]), "+f"(acc[0][3])
                : "r"(sA[tap][0]), "r"(sA[tap][1]), "r"(sA[tap][2]), "r"(sA[tap][3]),
                  "r"(bb[0]), "r"(bb[1]));
            asm("mma.sync.aligned.m16n8k16.row.col.f32.f16.f16.f32 "
                "{%0,%1,%2,%3}, {%4,%5,%6,%7}, {%8,%9}, {%0,%1,%2,%3};"
                : "+f"(acc[1][0]), "+f"(acc[1][1]), "+f"(acc[1][2]), "+f"(acc[1][3])
                : "r"(sA[tap][0]), "r"(sA[tap][1]), "r"(sA[tap][2]), "r"(sA[tap][3]),
                  "r"(bb[2]), "r"(bb[3]));
        }

        // ---- store: regs 0,1 -> oc=g ; regs 2,3 -> oc=g+8 ----
        #pragma unroll
        for (int nc = 0; nc < 2; ++nc) {
            int px = x0 + wrp * 16 + nc * 8 + 2 * i4;
            float* o0 = out + (((size_t)(n * 16 + g) * OUT_HW) + oy) * OUT_HW + px;
            float* o1 = o0 + (size_t)8 * OUT_HW * OUT_HW;
            *(float2*)o0 = make_float2(acc[nc][0], acc[nc][1]);
            *(float2*)o1 = make_float2(acc[nc][2], acc[nc][3]);
        }
        __syncthreads();
    }
}

extern "C" void kernel_launch(void* const* d_in, const int* in_sizes, int n_in,
                              void* d_out, int out_size) {
    const float* x = (const float*)d_in[0];
    const float* w = (const float*)d_in[1];
    float* out = (float*)d_out;

    dim3 grid(8, 64, 8);
    dim3 block(128);
    binconv_mma<<<grid, block>>>(x, w, out);
}

// round 16
// speedup vs baseline: 2.0051x; 1.3774x over previous
#include <cuda_runtime.h>
#include <cuda_fp16.h>
#include <cstdint>

// BinaryConv2d via warp-level HMMA implicit GEMM (mma.sync m16n8k16 f16).
// R16 = R15 (single-fp16, ldmatrix.x4 per tap, 18 mma/iter) +
// cross-iteration software pipelining: LDG it+1's rows at top of iter,
// compute it, cvt+STS it+1 after compute, ONE syncthreads per iteration.
// Ring buffer of 5 row slots (rows 2oy-1..2oy+3 concurrently live).

#define OUT_HW   512
#define CSTRIDE  48
#define ODD_OFS  3120            // 65 * 48, 16B-aligned
#define ROWBYTES 6192            // 3120 + 64*48
#define NRING    5

__device__ __forceinline__ void ldmx4(uint32_t* r, uint32_t addr) {
    asm("ldmatrix.sync.aligned.m8n8.x4.shared.b16 {%0,%1,%2,%3}, [%4];"
        : "=r"(r[0]), "=r"(r[1]), "=r"(r[2]), "=r"(r[3])
        : "r"(addr));
}

struct SR {                       // one staged row in registers
    float2 a2[4], b2[4];
    float  a0, b0;
};

__global__ void __launch_bounds__(128)
binconv_mma(const float* __restrict__ x,
            const float* __restrict__ w,
            float* __restrict__ out) {
    __shared__ __align__(16) unsigned char s_x[NRING * ROWBYTES];   // 30960 B

    const int tid  = threadIdx.x;
    const int wrp  = tid >> 5;
    const int lane = tid & 31;
    const int g    = lane >> 2;
    const int i4   = lane & 3;

    const int n   = blockIdx.z;
    const int x0  = blockIdx.x * 64;
    const int oy0 = blockIdx.y * 8;
    const int gx0 = 2 * x0 - 1;       // global input col of tile col 0

    const float* xn = x + ((size_t)n << 24);

    // ---- A fragments: signs as fp16 +/-1, register-resident ----
    uint32_t sA[9][4];
    #pragma unroll
    for (int tap = 0; tap < 9; ++tap) {
        #pragma unroll
        for (int q = 0; q < 4; ++q) {
            int oc = g + (q & 1) * 8;
            int c  = 2 * i4 + (q >> 1) * 8;
            uint32_t lo = (w[oc * 144 + c * 9 + tap]       == 1.f) ? 0x3C00u : 0xBC00u;
            uint32_t hi = (w[oc * 144 + (c + 1) * 9 + tap] == 1.f) ? 0x3C00u : 0xBC00u;
            sA[tap][q] = lo | (hi << 16);
        }
    }

    // ---- staging split into LDG half and cvt+STS half ----
    auto ldg_row = [&](int ia, SR& s) {
        const int cp = tid >> 4;
        const float* p0 = xn + ((size_t)(2 * cp) << 20)
                             + ((size_t)(ia < 0 ? 0 : ia) << 10);
        const float* p1 = p0 + (1 << 20);
        const bool rv = (ia >= 0);
        if ((tid & 15) == 0) {
            bool ok = rv && (gx0 >= 0);
            s.a0 = ok ? p0[gx0] : 0.f;
            s.b0 = ok ? p1[gx0] : 0.f;
        }
        #pragma unroll
        for (int v = 0; v < 4; ++v) {
            int m  = (tid & 15) + 16 * v;
            int gx = 2 * x0 + 2 * m;
            s.a2[v] = rv ? *(const float2*)(p0 + gx) : make_float2(0.f, 0.f);
            s.b2[v] = rv ? *(const float2*)(p1 + gx) : make_float2(0.f, 0.f);
        }
    };
    auto sts_row = [&](int ia, const SR& s) {
        unsigned char* rb = s_x + ((ia + NRING) % NRING) * ROWBYTES;
        const int cp = tid >> 4;
        if ((tid & 15) == 0)
            *(__half2*)(rb + cp * 4) = __floats2half2_rn(s.a0, s.b0);
        #pragma unroll
        for (int v = 0; v < 4; ++v) {
            int m = (tid & 15) + 16 * v;
            *(__half2*)(rb + ODD_OFS + m * CSTRIDE + cp * 4) =
                __floats2half2_rn(s.a2[v].x, s.b2[v].x);       // tile col 1+2m
            *(__half2*)(rb + (m + 1) * CSTRIDE + cp * 4) =
                __floats2half2_rn(s.a2[v].y, s.b2[v].y);       // tile col 2+2m
        }
    };

    uint32_t sbase;
    asm("{ .reg .u64 t; cvta.to.shared.u64 t, %1; cvt.u32.u64 %0, t; }"
        : "=r"(sbase) : "l"((const void*)s_x));
    const uint32_t pslot =
        (uint32_t)(wrp * 16 + (lane & 7) + ((lane >> 4) << 3));
    const uint32_t lane_off = pslot * CSTRIDE + (uint32_t)((lane >> 3) & 1) * 16u;
    const uint32_t offj[3] = { 0u, (uint32_t)ODD_OFS, (uint32_t)CSTRIDE };

    // ---- prologue: stage rows for it=0 ----
    {
        const int iy0 = 2 * oy0 - 1;
        SR r0, r1;
        ldg_row(iy0,     r0);
        ldg_row(iy0 + 1, r1);
        sts_row(iy0,     r0);
        sts_row(iy0 + 1, r1);
        ldg_row(iy0 + 2, r0);
        sts_row(iy0 + 2, r0);
    }
    __syncthreads();

    #pragma unroll 1
    for (int it = 0; it < 8; ++it) {
        const int oy  = oy0 + it;
        const int iy0 = 2 * oy - 1;

        // (1) issue LDGs for it+1's two new rows (latency hidden by compute)
        SR r0, r1;
        if (it < 7) {
            ldg_row(iy0 + 3, r0);
            ldg_row(iy0 + 4, r1);
        }

        // (2) compute it from ring slots iy0..iy0+2
        uint32_t rb3[3];
        #pragma unroll
        for (int r = 0; r < 3; ++r)
            rb3[r] = sbase
                   + (uint32_t)(((iy0 + r + NRING) % NRING) * ROWBYTES)
                   + lane_off;

        float acc[2][4];
        #pragma unroll
        for (int nc = 0; nc < 2; ++nc)
            acc[nc][0] = acc[nc][1] = acc[nc][2] = acc[nc][3] = 0.f;

        #pragma unroll
        for (int tap = 0; tap < 9; ++tap) {
            uint32_t bb[4];
            ldmx4(bb, rb3[tap / 3] + offj[tap % 3]);
            asm("mma.sync.aligned.m16n8k16.row.col.f32.f16.f16.f32 "
                "{%0,%1,%2,%3}, {%4,%5,%6,%7}, {%8,%9}, {%0,%1,%2,%3};"
                : "+f"(acc[0][0]), "+f"(acc[0][1]), "+f"(acc[0][2]), "+f"(acc[0][3])
                : "r"(sA[tap][0]), "r"(sA[tap][1]), "r"(sA[tap][2]), "r"(sA[tap][3]),
                  "r"(bb[0]), "r"(bb[1]));
            asm("mma.sync.aligned.m16n8k16.row.col.f32.f16.f16.f32 "
                "{%0,%1,%2,%3}, {%4,%5,%6,%7}, {%8,%9}, {%0,%1,%2,%3};"
                : "+f"(acc[1][0]), "+f"(acc[1][1]), "+f"(acc[1][2]), "+f"(acc[1][3])
                : "r"(sA[tap][0]), "r"(sA[tap][1]), "r"(sA[tap][2]), "r"(sA[tap][3]),
                  "r"(bb[2]), "r"(bb[3]));
        }

        // ---- store: regs 0,1 -> oc=g ; regs 2,3 -> oc=g+8 ----
        #pragma unroll
        for (int nc = 0; nc < 2; ++nc) {
            int px = x0 + wrp * 16 + nc * 8 + 2 * i4;
            float* o0 = out + (((size_t)(n * 16 + g) * OUT_HW) + oy) * OUT_HW + px;
            float* o1 = o0 + (size_t)8 * OUT_HW * OUT_HW;
            *(float2*)o0 = make_float2(acc[nc][0], acc[nc][1]);
            *(float2*)o1 = make_float2(acc[nc][2], acc[nc][3]);
        }

        // (3) cvt+STS it+1's rows into slots last read at it-1 (WAR-safe)
        if (it < 7) {
            sts_row(iy0 + 3, r0);
            sts_row(iy0 + 4, r1);
        }

        // (4) single barrier: staged rows visible, ring reuse ordered
        __syncthreads();
    }
}

extern "C" void kernel_launch(void* const* d_in, const int* in_sizes, int n_in,
                              void* d_out, int out_size) {
    const float* x = (const float*)d_in[0];
    const float* w = (const float*)d_in[1];
    float* out = (float*)d_out;

    dim3 grid(8, 64, 8);
    dim3 block(128);
    binconv_mma<<<grid, block>>>(x, w, out);
}